// round 15
// baseline (speedup 1.0000x reference)
#include <cuda_runtime.h>
#include <cstdint>
#include <cstddef>

// Problem constants
#define BATCH  32
#define SEQ    1024
#define INDIM  128
#define HID    512
#define LAYERS 3

// Recurrence decomposition: 16 batch groups (2 batches) x 8 j-groups (64 cols)
#define GB 16
#define GJ 8

// ---------------- device scratch (allocation-free rule) ------------------------
__device__ float g_P[(size_t)BATCH * SEQ * HID];   // pre-activations, current layer
__device__ float g_O[(size_t)BATCH * SEQ * HID];   // layer output sequence
__device__ float g_hbuf[2][BATCH * HID];           // double-buffered hidden state
__device__ int   g_flags[GB * GJ];                 // monotonic per-CTA step flags

// ---------------- PTX helpers --------------------------------------------------
__device__ __forceinline__ unsigned long long pack2(float x, float y) {
    unsigned long long r;
    asm("mov.b64 %0, {%1, %2};" : "=l"(r) : "f"(x), "f"(y));
    return r;
}
__device__ __forceinline__ unsigned long long ffma2(unsigned long long a,
                                                    unsigned long long b,
                                                    unsigned long long c) {
    unsigned long long d;
    asm("fma.rn.f32x2 %0, %1, %2, %3;" : "=l"(d) : "l"(a), "l"(b), "l"(c));
    return d;
}
__device__ __forceinline__ float pairsum(unsigned long long p) {
    unsigned lo, hi;
    asm("mov.b64 {%0, %1}, %2;" : "=r"(lo), "=r"(hi) : "l"(p));
    return __uint_as_float(lo) + __uint_as_float(hi);
}
__device__ __forceinline__ int ld_acquire_gpu(const int* p) {
    int v;
    asm volatile("ld.global.acquire.gpu.b32 %0, [%1];" : "=r"(v) : "l"(p));
    return v;
}
__device__ __forceinline__ void st_relaxed_gpu(int* p, int v) {
    asm volatile("st.global.relaxed.gpu.b32 [%0], %1;" :: "l"(p), "r"(v));
}
__device__ __forceinline__ float ldg_nc_f32(const float* p) {
    float v;
    asm volatile("ld.global.nc.f32 %0, [%1];" : "=f"(v) : "l"(p));
    return v;
}

// ==============================================================================
// Projection GEMM:  g_P[r][n] = sum_k A[r][k] * W[n][k] + bias[n]
// 128x128 tile, BK=8, 256 threads, 8x8 microtile. Block (0,0) resets the
// recurrence flags (stream order: lands before the following rec_kernel).
// ==============================================================================
__global__ __launch_bounds__(256) void proj_kernel(
    const float* __restrict__ Aext, int useO,
    const float* __restrict__ W,
    const float* __restrict__ bias,
    int K)
{
    const float* A = useO ? g_O : Aext;

    __shared__ float As[8][128];
    __shared__ float Bs[8][128];

    int tid = threadIdx.x;
    if (blockIdx.x == 0 && blockIdx.y == 0 && tid < GB * GJ) g_flags[tid] = 0;

    int m0 = blockIdx.y * 128;
    int n0 = blockIdx.x * 128;

    int lr = tid >> 1;
    int lk = (tid & 1) * 4;

    const float4* Aload = (const float4*)(A + (size_t)(m0 + lr) * K + lk);
    const float4* Wload = (const float4*)(W + (size_t)(n0 + lr) * K + lk);

    int tm = tid >> 4;
    int tn = tid & 15;

    float acc[8][8];
    #pragma unroll
    for (int i = 0; i < 8; i++)
        #pragma unroll
        for (int j = 0; j < 8; j++) acc[i][j] = 0.f;

    for (int k0 = 0; k0 < K; k0 += 8) {
        float4 av = Aload[k0 >> 2];
        float4 wv = Wload[k0 >> 2];
        As[lk + 0][lr] = av.x; As[lk + 1][lr] = av.y;
        As[lk + 2][lr] = av.z; As[lk + 3][lr] = av.w;
        Bs[lk + 0][lr] = wv.x; Bs[lk + 1][lr] = wv.y;
        Bs[lk + 2][lr] = wv.z; Bs[lk + 3][lr] = wv.w;
        __syncthreads();

        #pragma unroll
        for (int kk = 0; kk < 8; kk++) {
            float a[8], b[8];
            *(float4*)(a)     = *(const float4*)(&As[kk][tm * 8]);
            *(float4*)(a + 4) = *(const float4*)(&As[kk][tm * 8 + 4]);
            *(float4*)(b)     = *(const float4*)(&Bs[kk][tn * 8]);
            *(float4*)(b + 4) = *(const float4*)(&Bs[kk][tn * 8 + 4]);
            #pragma unroll
            for (int i = 0; i < 8; i++)
                #pragma unroll
                for (int j = 0; j < 8; j++)
                    acc[i][j] += a[i] * b[j];
        }
        __syncthreads();
    }

    float bv[8];
    #pragma unroll
    for (int j = 0; j < 8; j++) bv[j] = bias[n0 + tn * 8 + j];

    #pragma unroll
    for (int i = 0; i < 8; i++) {
        float* crow = g_P + (size_t)(m0 + tm * 8 + i) * HID + n0 + tn * 8;
        float4 v0 = make_float4(acc[i][0] + bv[0], acc[i][1] + bv[1],
                                acc[i][2] + bv[2], acc[i][3] + bv[3]);
        float4 v1 = make_float4(acc[i][4] + bv[4], acc[i][5] + bv[5],
                                acc[i][6] + bv[6], acc[i][7] + bv[7]);
        *(float4*)(crow)     = v0;
        *(float4*)(crow + 4) = v1;
    }
}

// ==============================================================================
// Persistent recurrence kernel — R14 protocol with PER-WARP producer gating.
//   h_t = tanh( g_P[b][t][:] + W_hh @ h_{t-1} + b_hh )
// Warp w depends only on producer CTA w's j-slice (== its k-chunk), so lane0
// of warp w polls flag[w] (nanosleep backoff), loads its 128 floats, and dots
// immediately. The reduce barrier is the all-warp join; BAR2 orders ring
// stores before tid0's threadfence+flag release (R14's proven release).
// Slot safety: P's 8 warps collectively verify flags[0..7] >= t before BAR1,
// so P's ring write of slot t&1 happens after every peer finished step t-1.
// ==============================================================================
__global__ __launch_bounds__(256, 1) void rec_kernel(
    const float* __restrict__ Whh,        // [512][512]
    const float* __restrict__ h0l,        // [32][512]
    const float* __restrict__ bhh,        // [512]
    float* __restrict__ out_ext, int useO,
    float* __restrict__ hidden_out)       // [32][512]
{
    float* outbuf = useO ? g_O : out_ext;

    const int bg = blockIdx.x & (GB - 1);   // 0..15
    const int jg = blockIdx.x >> 4;         // 0..7
    const int b0 = bg * 2;
    const int jbase = jg * 64;

    const int tid  = threadIdx.x;
    const int w    = tid >> 5;              // warp -> k-chunk / producer peer
    const int lane = tid & 31;

    __shared__ __align__(16) float sh[8][2][64];   // [w][batch][k] warp-private
    __shared__ float red[8][2][64];                // [k-chunk][batch][jlocal]

    // W_hh slice in registers, f32x2-packed along k:
    //   Wr0 -> row jbase+lane, Wr1 -> row jbase+lane+32
    unsigned long long Wr0[32], Wr1[32];
    {
        const float4* r0 = (const float4*)(Whh + (size_t)(jbase + lane) * HID + w * 64);
        const float4* r1 = (const float4*)(Whh + (size_t)(jbase + lane + 32) * HID + w * 64);
        #pragma unroll
        for (int i = 0; i < 16; i++) {
            float4 v0 = r0[i];
            Wr0[2 * i]     = pack2(v0.x, v0.y);
            Wr0[2 * i + 1] = pack2(v0.z, v0.w);
            float4 v1 = r1[i];
            Wr1[2 * i]     = pack2(v1.x, v1.y);
            Wr1[2 * i + 1] = pack2(v1.z, v1.w);
        }
    }

    int*       my_flag = &g_flags[bg * GJ + jg];
    const int* w_flag  = &g_flags[bg * GJ + w];

    // Warp-private staging load: lane -> (batch, 4 k-values) within chunk w
    const int sb = lane >> 4;               // 0/1
    const int sk = (lane & 15) * 4;

    // Reduce mapping: tid<128 -> output (batch ob, column jl)
    const int ob = tid >> 6;
    const int jl = tid & 63;
    const float bias_r = (tid < 128) ? bhh[jbase + jl] : 0.f;
    const float* prep = g_P + ((size_t)(b0 + ob) * SEQ) * HID + jbase + jl;

    for (int t = 0; t < SEQ; t++) {
        // Pre-activation prefetch (DRAM latency overlapped with wait + dot)
        float pre_v = 0.f;
        if (tid < 128) pre_v = ldg_nc_f32(prep + (size_t)t * HID);

        // ---- per-warp gate + warp-private chunk load ----
        const float* src;
        if (t == 0) {
            src = h0l + (size_t)b0 * HID;
        } else {
            if (lane == 0)
                while (ld_acquire_gpu(w_flag) < t) __nanosleep(32);
            __syncwarp();
            src = g_hbuf[(t - 1) & 1] + (size_t)b0 * HID;
        }
        {
            float4 v = *(const float4*)(src + (size_t)sb * HID + w * 64 + sk);
            *(float4*)&sh[w][sb][sk] = v;
        }
        __syncwarp();

        // ---- dot over this warp's 64-wide k chunk (f32x2 packed) ----
        const unsigned long long* hA = (const unsigned long long*)(&sh[w][0][0]);
        const unsigned long long* hB = (const unsigned long long*)(&sh[w][1][0]);
        unsigned long long a00 = 0ull, a01 = 0ull, a10 = 0ull, a11 = 0ull;
        #pragma unroll
        for (int kk = 0; kk < 32; kk++) {
            unsigned long long ha = hA[kk];   // LDS.64 broadcast
            unsigned long long hb = hB[kk];
            a00 = ffma2(Wr0[kk], ha, a00);
            a01 = ffma2(Wr0[kk], hb, a01);
            a10 = ffma2(Wr1[kk], ha, a10);
            a11 = ffma2(Wr1[kk], hb, a11);
        }
        red[w][0][lane]      = pairsum(a00);
        red[w][1][lane]      = pairsum(a01);
        red[w][0][lane + 32] = pairsum(a10);
        red[w][1][lane + 32] = pairsum(a11);
        __syncthreads();                       // BAR1: join all 8 producers' partials

        // ---- reduce 8 k-chunks, tanh, ring store ----
        float val = 0.f;
        if (tid < 128) {
            float s = pre_v + bias_r;
            #pragma unroll
            for (int ww = 0; ww < 8; ww++) s += red[ww][ob][jl];
            val = tanhf(s);
            if (t < SEQ - 1)
                g_hbuf[t & 1][(size_t)(b0 + ob) * HID + jbase + jl] = val;
        }
        __syncthreads();                       // BAR2: ring stores before release

        // ---- release (R14 protocol): fence + relaxed flag store ----
        if (t < SEQ - 1 && tid == 0) {
            __threadfence();
            st_relaxed_gpu(my_flag, t + 1);
        }

        // ---- off-critical-path DRAM stores ----
        if (tid < 128) {
            outbuf[((size_t)(b0 + ob) * SEQ + t) * HID + jbase + jl] = val;
            if (t == SEQ - 1)
                hidden_out[(size_t)(b0 + ob) * HID + jbase + jl] = val;
        }
    }
}

// ==============================================================================
extern "C" void kernel_launch(void* const* d_in, const int* in_sizes, int n_in,
                              void* d_out, int out_size)
{
    const float* x     = (const float*)d_in[0];   // [32,1024,128]
    const float* h0    = (const float*)d_in[1];   // [3,32,512]
    const float* w_ih0 = (const float*)d_in[2];   // [512,128]
    const float* w_ihs = (const float*)d_in[3];   // [2,512,512]
    const float* w_hhs = (const float*)d_in[4];   // [3,512,512]
    const float* b_ihs = (const float*)d_in[5];   // [3,512]
    const float* b_hhs = (const float*)d_in[6];   // [3,512]

    float* out    = (float*)d_out;
    float* hidden = out;                                   // [3][32][512]
    float* outseq = out + (size_t)LAYERS * BATCH * HID;    // [32*1024][512]

    dim3 pg(HID / 128, (BATCH * SEQ) / 128);               // (4, 256)

    // ---- layer 0 ----
    proj_kernel<<<pg, 256>>>(x, 0, w_ih0, b_ihs + 0 * HID, INDIM);
    rec_kernel<<<GB * GJ, 256>>>(w_hhs + (size_t)0 * HID * HID,
                                 h0 + (size_t)0 * BATCH * HID,
                                 b_hhs + 0 * HID,
                                 nullptr, 1,
                                 hidden + (size_t)0 * BATCH * HID);
    // ---- layer 1 ----
    proj_kernel<<<pg, 256>>>(nullptr, 1, w_ihs + (size_t)0 * HID * HID,
                             b_ihs + 1 * HID, HID);
    rec_kernel<<<GB * GJ, 256>>>(w_hhs + (size_t)1 * HID * HID,
                                 h0 + (size_t)1 * BATCH * HID,
                                 b_hhs + 1 * HID,
                                 nullptr, 1,
                                 hidden + (size_t)1 * BATCH * HID);
    // ---- layer 2 (sequence straight into d_out) ----
    proj_kernel<<<pg, 256>>>(nullptr, 1, w_ihs + (size_t)1 * HID * HID,
                             b_ihs + 2 * HID, HID);
    rec_kernel<<<GB * GJ, 256>>>(w_hhs + (size_t)2 * HID * HID,
                                 h0 + (size_t)2 * BATCH * HID,
                                 b_hhs + 2 * HID,
                                 outseq, 0,
                                 hidden + (size_t)2 * BATCH * HID);
}

// round 16
// speedup vs baseline: 1.7083x; 1.7083x over previous
#include <cuda_runtime.h>
#include <cstdint>
#include <cstddef>

// Problem constants
#define BATCH  32
#define SEQ    1024
#define INDIM  128
#define HID    512
#define LAYERS 3

// Recurrence decomposition (R14-proven): 16 batch groups (2 batches) x 8 j-groups
#define GB 16
#define GJ 8

#define WI_PAD 516   // padded row stride (floats) for W_ih SMEM slice: conflict-free

// ---------------- device scratch (allocation-free rule) ------------------------
__device__ float g_P[(size_t)BATCH * SEQ * HID];   // pre-activations (in-place per layer)
__device__ float g_hbuf[2][BATCH * HID];           // double-buffered hidden state
__device__ int   g_flags[LAYERS][GB * GJ];         // per-layer monotonic step flags

// ---------------- PTX helpers --------------------------------------------------
__device__ __forceinline__ unsigned long long pack2(float x, float y) {
    unsigned long long r;
    asm("mov.b64 %0, {%1, %2};" : "=l"(r) : "f"(x), "f"(y));
    return r;
}
__device__ __forceinline__ unsigned long long ffma2(unsigned long long a,
                                                    unsigned long long b,
                                                    unsigned long long c) {
    unsigned long long d;
    asm("fma.rn.f32x2 %0, %1, %2, %3;" : "=l"(d) : "l"(a), "l"(b), "l"(c));
    return d;
}
__device__ __forceinline__ float pairsum(unsigned long long p) {
    unsigned lo, hi;
    asm("mov.b64 {%0, %1}, %2;" : "=r"(lo), "=r"(hi) : "l"(p));
    return __uint_as_float(lo) + __uint_as_float(hi);
}
__device__ __forceinline__ int ld_acquire_gpu(const int* p) {
    int v;
    asm volatile("ld.global.acquire.gpu.b32 %0, [%1];" : "=r"(v) : "l"(p));
    return v;
}
__device__ __forceinline__ void st_relaxed_gpu(int* p, int v) {
    asm volatile("st.global.relaxed.gpu.b32 [%0], %1;" :: "l"(p), "r"(v));
}
__device__ __forceinline__ float ldg_nc_f32(const float* p) {
    float v;
    asm volatile("ld.global.nc.f32 %0, [%1];" : "=f"(v) : "l"(p));
    return v;
}

// ==============================================================================
// Projection GEMM (layer 0 only):  g_P[r][n] = sum_k x[r][k] * W[n][k] + b[n]
// 128x128 tile, BK=8, 256 threads, 8x8 microtile. Block (0,0) resets ALL
// layers' flags (stream order: lands before the rec chain).
// ==============================================================================
__global__ __launch_bounds__(256) void proj_kernel(
    const float* __restrict__ A,
    const float* __restrict__ W,
    const float* __restrict__ bias,
    int K)
{
    __shared__ float As[8][128];
    __shared__ float Bs[8][128];

    int tid = threadIdx.x;
    if (blockIdx.x == 0 && blockIdx.y == 0) {
        for (int i = tid; i < LAYERS * GB * GJ; i += 256)
            (&g_flags[0][0])[i] = 0;
    }

    int m0 = blockIdx.y * 128;
    int n0 = blockIdx.x * 128;

    int lr = tid >> 1;
    int lk = (tid & 1) * 4;

    const float4* Aload = (const float4*)(A + (size_t)(m0 + lr) * K + lk);
    const float4* Wload = (const float4*)(W + (size_t)(n0 + lr) * K + lk);

    int tm = tid >> 4;
    int tn = tid & 15;

    float acc[8][8];
    #pragma unroll
    for (int i = 0; i < 8; i++)
        #pragma unroll
        for (int j = 0; j < 8; j++) acc[i][j] = 0.f;

    for (int k0 = 0; k0 < K; k0 += 8) {
        float4 av = Aload[k0 >> 2];
        float4 wv = Wload[k0 >> 2];
        As[lk + 0][lr] = av.x; As[lk + 1][lr] = av.y;
        As[lk + 2][lr] = av.z; As[lk + 3][lr] = av.w;
        Bs[lk + 0][lr] = wv.x; Bs[lk + 1][lr] = wv.y;
        Bs[lk + 2][lr] = wv.z; Bs[lk + 3][lr] = wv.w;
        __syncthreads();

        #pragma unroll
        for (int kk = 0; kk < 8; kk++) {
            float a[8], b[8];
            *(float4*)(a)     = *(const float4*)(&As[kk][tm * 8]);
            *(float4*)(a + 4) = *(const float4*)(&As[kk][tm * 8 + 4]);
            *(float4*)(b)     = *(const float4*)(&Bs[kk][tn * 8]);
            *(float4*)(b + 4) = *(const float4*)(&Bs[kk][tn * 8 + 4]);
            #pragma unroll
            for (int i = 0; i < 8; i++)
                #pragma unroll
                for (int j = 0; j < 8; j++)
                    acc[i][j] += a[i] * b[j];
        }
        __syncthreads();
    }

    float bv[8];
    #pragma unroll
    for (int j = 0; j < 8; j++) bv[j] = bias[n0 + tn * 8 + j];

    #pragma unroll
    for (int i = 0; i < 8; i++) {
        float* crow = g_P + (size_t)(m0 + tm * 8 + i) * HID + n0 + tn * 8;
        float4 v0 = make_float4(acc[i][0] + bv[0], acc[i][1] + bv[1],
                                acc[i][2] + bv[2], acc[i][3] + bv[3]);
        float4 v1 = make_float4(acc[i][4] + bv[4], acc[i][5] + bv[5],
                                acc[i][6] + bv[6], acc[i][7] + bv[7]);
        *(float4*)(crow)     = v0;
        *(float4*)(crow + 4) = v1;
    }
}

// ==============================================================================
// Persistent recurrence kernel (R14 protocol, byte-for-byte) + fused NEXT-layer
// input projection computed in the post-release slack:
//   rec:   h_t = tanh( g_P[b][t] + W_hh h_{t-1} + b_hh )
//   fused: g_P[b][t-1] <- W_ih_next h_{t-1} + b_ih_next   (in place, own slice)
// The fused row t-1 was consumed by this same CTA at step t-1 -> in-place safe.
// With fusion the loop runs SEQ+1 iterations (last one: fused row SEQ-1 only),
// ring store + release extended to t=SEQ-1 so the extra gate can pass.
// ==============================================================================
__global__ __launch_bounds__(256, 1) void rec_kernel(
    const float* __restrict__ Whh,        // [512][512] this layer
    const float* __restrict__ h0l,        // [32][512]  this layer
    const float* __restrict__ bhh,        // [512]      this layer
    const float* __restrict__ Wih_next,   // [512][512] next layer, or nullptr
    const float* __restrict__ bih_next,   // [512]      next layer, or nullptr
    float* __restrict__ outseq,           // [32][1024][512] or nullptr
    float* __restrict__ hidden_out,       // [32][512]  this layer
    int layer)
{
    const bool fuse = (Wih_next != nullptr);

    const int bg = blockIdx.x & (GB - 1);   // 0..15
    const int jg = blockIdx.x >> 4;         // 0..7
    const int b0 = bg * 2;
    const int jbase = jg * 64;

    const int tid  = threadIdx.x;
    const int w    = tid >> 5;              // warp -> 64-wide k chunk
    const int lane = tid & 31;

    __shared__ __align__(16) float h_sh[2][HID];   // [batch][k]
    __shared__ float red[8][2][64];                // [k-chunk][batch][jlocal]
    extern __shared__ float Wi_sh[];               // [64][WI_PAD] fused W_ih slice

    // ---- W_hh slice in registers, f32x2-packed along k ----
    unsigned long long Wr0[32], Wr1[32];
    {
        const float4* r0 = (const float4*)(Whh + (size_t)(jbase + lane) * HID + w * 64);
        const float4* r1 = (const float4*)(Whh + (size_t)(jbase + lane + 32) * HID + w * 64);
        #pragma unroll
        for (int i = 0; i < 16; i++) {
            float4 v0 = r0[i];
            Wr0[2 * i]     = pack2(v0.x, v0.y);
            Wr0[2 * i + 1] = pack2(v0.z, v0.w);
            float4 v1 = r1[i];
            Wr1[2 * i]     = pack2(v1.x, v1.y);
            Wr1[2 * i + 1] = pack2(v1.z, v1.w);
        }
    }

    // ---- fused W_ih slice into SMEM (rows jbase..jbase+63, padded stride) ----
    if (fuse) {
        for (int idx = tid; idx < 64 * (HID / 4); idx += 256) {
            int row = idx >> 7;             // /128
            int q   = (idx & 127) * 4;
            float4 v = *(const float4*)(Wih_next + (size_t)(jbase + row) * HID + q);
            *(float4*)&Wi_sh[(size_t)row * WI_PAD + q] = v;
        }
    }

    int* my_flag = &g_flags[layer][bg * GJ + jg];
    const int* flags_l = &g_flags[layer][bg * GJ];

    // Reduce mapping: tid<128 -> output (batch ob, column jl)
    const int ob = tid >> 6;
    const int jl = tid & 63;
    const float bias_r  = (tid < 128) ? bhh[jbase + jl] : 0.f;
    const float bias_in = (fuse && tid < 128) ? bih_next[jbase + jl] : 0.f;
    float* prow = g_P + ((size_t)(b0 + ob) * SEQ) * HID + jbase + jl;

    // Cooperative h load mapping: thread -> (batch, float4 of k)
    const int cb = tid >> 7;                // 0/1
    const int ck = (tid & 127) * 4;

    const int TMAX = fuse ? SEQ + 1 : SEQ;

    for (int t = 0; t < TMAX; t++) {
        const bool rec_step = (t < SEQ);

        // Pre-activation prefetch (DRAM latency overlapped with gate + load)
        float pre_v = 0.f;
        if (rec_step && tid < 128) pre_v = ldg_nc_f32(prow + (size_t)t * HID);

        // ---- gate + cooperative load of full h_{t-1} (R14 protocol) ----
        if (t == 0) {
            float4 v = *(const float4*)(h0l + (size_t)(b0 + cb) * HID + ck);
            *(float4*)&h_sh[cb][ck] = v;
        } else {
            if (tid < GJ) {
                while (ld_acquire_gpu(&flags_l[tid]) < t) __nanosleep(32);
            }
            __syncthreads();
            const float* hb = g_hbuf[(t - 1) & 1];
            float4 v = *(const float4*)(hb + (size_t)(b0 + cb) * HID + ck);
            *(float4*)&h_sh[cb][ck] = v;
        }
        __syncthreads();

        float val = 0.f;
        if (rec_step) {
            // ---- recurrent dot over this warp's 64-wide k chunk ----
            const unsigned long long* hA = (const unsigned long long*)(&h_sh[0][w * 64]);
            const unsigned long long* hB = (const unsigned long long*)(&h_sh[1][w * 64]);
            unsigned long long a00 = 0ull, a01 = 0ull, a10 = 0ull, a11 = 0ull;
            #pragma unroll
            for (int kk = 0; kk < 32; kk++) {
                unsigned long long ha = hA[kk];
                unsigned long long hb = hB[kk];
                a00 = ffma2(Wr0[kk], ha, a00);
                a01 = ffma2(Wr0[kk], hb, a01);
                a10 = ffma2(Wr1[kk], ha, a10);
                a11 = ffma2(Wr1[kk], hb, a11);
            }
            red[w][0][lane]      = pairsum(a00);
            red[w][1][lane]      = pairsum(a01);
            red[w][0][lane + 32] = pairsum(a10);
            red[w][1][lane + 32] = pairsum(a11);
            __syncthreads();                   // BAR1

            // ---- reduce, tanh, ring store ----
            if (tid < 128) {
                float s = pre_v + bias_r;
                #pragma unroll
                for (int ww = 0; ww < 8; ww++) s += red[ww][ob][jl];
                val = tanhf(s);
                // with fusion keep the last ring slot (needed by the extra gate)
                if (fuse ? true : (t < SEQ - 1))
                    g_hbuf[t & 1][(size_t)(b0 + ob) * HID + jbase + jl] = val;
            }
            __syncthreads();                   // BAR2: ring stores before release

            // ---- release (R14): fence + relaxed flag store ----
            if (tid == 0 && (fuse ? (t < SEQ) : (t < SEQ - 1))) {
                __threadfence();
                st_relaxed_gpu(my_flag, t + 1);
            }

            // ---- off-critical-path DRAM stores ----
            if (tid < 128) {
                if (outseq)
                    outseq[((size_t)(b0 + ob) * SEQ + t) * HID + jbase + jl] = val;
                if (t == SEQ - 1)
                    hidden_out[(size_t)(b0 + ob) * HID + jbase + jl] = val;
            }
        }

        // ---- fused next-layer projection for row t-1 (post-release slack) ----
        if (fuse && t > 0) {
            const unsigned long long* hA = (const unsigned long long*)(&h_sh[0][w * 64]);
            const unsigned long long* hB = (const unsigned long long*)(&h_sh[1][w * 64]);
            const unsigned long long* w0 =
                (const unsigned long long*)(&Wi_sh[(size_t)lane * WI_PAD + w * 64]);
            const unsigned long long* w1 =
                (const unsigned long long*)(&Wi_sh[(size_t)(lane + 32) * WI_PAD + w * 64]);
            unsigned long long a00 = 0ull, a01 = 0ull, a10 = 0ull, a11 = 0ull;
            #pragma unroll
            for (int kk = 0; kk < 32; kk++) {
                unsigned long long ha = hA[kk];
                unsigned long long hb = hB[kk];
                a00 = ffma2(w0[kk], ha, a00);
                a01 = ffma2(w0[kk], hb, a01);
                a10 = ffma2(w1[kk], ha, a10);
                a11 = ffma2(w1[kk], hb, a11);
            }
            red[w][0][lane]      = pairsum(a00);
            red[w][1][lane]      = pairsum(a01);
            red[w][0][lane + 32] = pairsum(a10);
            red[w][1][lane + 32] = pairsum(a11);
            __syncthreads();                   // BAR3

            if (tid < 128) {
                float s = bias_in;
                #pragma unroll
                for (int ww = 0; ww < 8; ww++) s += red[ww][ob][jl];
                // in-place: this row+slice was consumed by THIS CTA at step t-1
                prow[(size_t)(t - 1) * HID] = s;
            }
            // h_sh/red reuse at t+1 is ordered by the gate barrier of t+1
        }
    }
}

// ==============================================================================
extern "C" void kernel_launch(void* const* d_in, const int* in_sizes, int n_in,
                              void* d_out, int out_size)
{
    const float* x     = (const float*)d_in[0];   // [32,1024,128]
    const float* h0    = (const float*)d_in[1];   // [3,32,512]
    const float* w_ih0 = (const float*)d_in[2];   // [512,128]
    const float* w_ihs = (const float*)d_in[3];   // [2,512,512]
    const float* w_hhs = (const float*)d_in[4];   // [3,512,512]
    const float* b_ihs = (const float*)d_in[5];   // [3,512]
    const float* b_hhs = (const float*)d_in[6];   // [3,512]

    float* out    = (float*)d_out;
    float* hidden = out;                                   // [3][32][512]
    float* outseq = out + (size_t)LAYERS * BATCH * HID;    // [32][1024][512]

    const int wi_smem = 64 * WI_PAD * 4;                   // 132 KB dynamic

    static int smem_set = 0;
    if (!smem_set) {
        cudaFuncSetAttribute(rec_kernel,
                             cudaFuncAttributeMaxDynamicSharedMemorySize, wi_smem);
        smem_set = 1;
    }

    // Layer-0 input projection (also resets all flags; stream-ordered)
    dim3 pg(HID / 128, (BATCH * SEQ) / 128);               // (4, 256)
    proj_kernel<<<pg, 256>>>(x, w_ih0, b_ihs, INDIM);

    // ---- layer 0: rec + fused proj for layer 1 ----
    rec_kernel<<<GB * GJ, 256, wi_smem>>>(
        w_hhs + (size_t)0 * HID * HID, h0 + (size_t)0 * BATCH * HID,
        b_hhs + 0 * HID,
        w_ihs + (size_t)0 * HID * HID, b_ihs + 1 * HID,
        nullptr, hidden + (size_t)0 * BATCH * HID, 0);

    // ---- layer 1: rec + fused proj for layer 2 ----
    rec_kernel<<<GB * GJ, 256, wi_smem>>>(
        w_hhs + (size_t)1 * HID * HID, h0 + (size_t)1 * BATCH * HID,
        b_hhs + 1 * HID,
        w_ihs + (size_t)1 * HID * HID, b_ihs + 2 * HID,
        nullptr, hidden + (size_t)1 * BATCH * HID, 1);

    // ---- layer 2: rec only, sequence straight into d_out ----
    rec_kernel<<<GB * GJ, 256, wi_smem>>>(
        w_hhs + (size_t)2 * HID * HID, h0 + (size_t)2 * BATCH * HID,
        b_hhs + 2 * HID,
        nullptr, nullptr,
        outseq, hidden + (size_t)2 * BATCH * HID, 2);
}

// round 17
// speedup vs baseline: 1.7425x; 1.0200x over previous
#include <cuda_runtime.h>
#include <cstdint>
#include <cstddef>

// Problem constants
#define BATCH  32
#define SEQ    1024
#define INDIM  128
#define HID    512
#define LAYERS 3

// Recurrence decomposition (R14-proven): 16 batch groups (2 batches) x 8 j-groups
#define GB 16
#define GJ 8

#define WI_PAD 516   // padded row stride (floats) for W_ih SMEM slice: conflict-free

// ---------------- device scratch (allocation-free rule) ------------------------
__device__ float g_P[(size_t)BATCH * SEQ * HID];   // pre-activations (in-place per layer)
__device__ float g_hbuf[2][BATCH * HID];           // double-buffered hidden state
__device__ int   g_flags[LAYERS][GB * GJ];         // per-layer monotonic step flags

// ---------------- PTX helpers --------------------------------------------------
__device__ __forceinline__ unsigned long long pack2(float x, float y) {
    unsigned long long r;
    asm("mov.b64 %0, {%1, %2};" : "=l"(r) : "f"(x), "f"(y));
    return r;
}
__device__ __forceinline__ unsigned long long ffma2(unsigned long long a,
                                                    unsigned long long b,
                                                    unsigned long long c) {
    unsigned long long d;
    asm("fma.rn.f32x2 %0, %1, %2, %3;" : "=l"(d) : "l"(a), "l"(b), "l"(c));
    return d;
}
__device__ __forceinline__ float pairsum(unsigned long long p) {
    unsigned lo, hi;
    asm("mov.b64 {%0, %1}, %2;" : "=r"(lo), "=r"(hi) : "l"(p));
    return __uint_as_float(lo) + __uint_as_float(hi);
}
__device__ __forceinline__ int ld_acquire_gpu(const int* p) {
    int v;
    asm volatile("ld.global.acquire.gpu.b32 %0, [%1];" : "=r"(v) : "l"(p));
    return v;
}
// Fence-free release: bar.sync (intra-CTA happens-before) + release store on the
// flag. Ring data moves L2-only (.cg), so no L1 flush (CCTL.IVALL) is needed.
// Correctness of this scheme was validated in R13 (passed, rel_err identical).
__device__ __forceinline__ void st_release_gpu(int* p, int v) {
    asm volatile("st.global.release.gpu.b32 [%0], %1;" :: "l"(p), "r"(v));
}
__device__ __forceinline__ float ldg_nc_f32(const float* p) {
    float v;
    asm volatile("ld.global.nc.f32 %0, [%1];" : "=f"(v) : "l"(p));
    return v;
}
__device__ __forceinline__ void stg_cg_f32(float* p, float v) {
    asm volatile("st.global.cg.f32 [%0], %1;" :: "l"(p), "f"(v));
}
__device__ __forceinline__ float4 ldg_cg_f32x4(const float* p) {
    float4 v;
    asm volatile("ld.global.cg.v4.f32 {%0, %1, %2, %3}, [%4];"
                 : "=f"(v.x), "=f"(v.y), "=f"(v.z), "=f"(v.w) : "l"(p));
    return v;
}

// ==============================================================================
// Projection GEMM (layer 0 only):  g_P[r][n] = sum_k x[r][k] * W[n][k] + b[n]
// 128x128 tile, BK=8, 256 threads, 8x8 microtile. Block (0,0) resets ALL
// layers' flags (stream order: lands before the rec chain).
// ==============================================================================
__global__ __launch_bounds__(256) void proj_kernel(
    const float* __restrict__ A,
    const float* __restrict__ W,
    const float* __restrict__ bias,
    int K)
{
    __shared__ float As[8][128];
    __shared__ float Bs[8][128];

    int tid = threadIdx.x;
    if (blockIdx.x == 0 && blockIdx.y == 0) {
        for (int i = tid; i < LAYERS * GB * GJ; i += 256)
            (&g_flags[0][0])[i] = 0;
    }

    int m0 = blockIdx.y * 128;
    int n0 = blockIdx.x * 128;

    int lr = tid >> 1;
    int lk = (tid & 1) * 4;

    const float4* Aload = (const float4*)(A + (size_t)(m0 + lr) * K + lk);
    const float4* Wload = (const float4*)(W + (size_t)(n0 + lr) * K + lk);

    int tm = tid >> 4;
    int tn = tid & 15;

    float acc[8][8];
    #pragma unroll
    for (int i = 0; i < 8; i++)
        #pragma unroll
        for (int j = 0; j < 8; j++) acc[i][j] = 0.f;

    for (int k0 = 0; k0 < K; k0 += 8) {
        float4 av = Aload[k0 >> 2];
        float4 wv = Wload[k0 >> 2];
        As[lk + 0][lr] = av.x; As[lk + 1][lr] = av.y;
        As[lk + 2][lr] = av.z; As[lk + 3][lr] = av.w;
        Bs[lk + 0][lr] = wv.x; Bs[lk + 1][lr] = wv.y;
        Bs[lk + 2][lr] = wv.z; Bs[lk + 3][lr] = wv.w;
        __syncthreads();

        #pragma unroll
        for (int kk = 0; kk < 8; kk++) {
            float a[8], b[8];
            *(float4*)(a)     = *(const float4*)(&As[kk][tm * 8]);
            *(float4*)(a + 4) = *(const float4*)(&As[kk][tm * 8 + 4]);
            *(float4*)(b)     = *(const float4*)(&Bs[kk][tn * 8]);
            *(float4*)(b + 4) = *(const float4*)(&Bs[kk][tn * 8 + 4]);
            #pragma unroll
            for (int i = 0; i < 8; i++)
                #pragma unroll
                for (int j = 0; j < 8; j++)
                    acc[i][j] += a[i] * b[j];
        }
        __syncthreads();
    }

    float bv[8];
    #pragma unroll
    for (int j = 0; j < 8; j++) bv[j] = bias[n0 + tn * 8 + j];

    #pragma unroll
    for (int i = 0; i < 8; i++) {
        float* crow = g_P + (size_t)(m0 + tm * 8 + i) * HID + n0 + tn * 8;
        float4 v0 = make_float4(acc[i][0] + bv[0], acc[i][1] + bv[1],
                                acc[i][2] + bv[2], acc[i][3] + bv[3]);
        float4 v1 = make_float4(acc[i][4] + bv[4], acc[i][5] + bv[5],
                                acc[i][6] + bv[6], acc[i][7] + bv[7]);
        *(float4*)(crow)     = v0;
        *(float4*)(crow + 4) = v1;
    }
}

// ==============================================================================
// Persistent recurrence kernel (R16 structure; fence-free release):
//   rec:   h_t = tanh( g_P[b][t] + W_hh h_{t-1} + b_hh )
//   fused: g_P[b][t-1] <- W_ih_next h_{t-1} + b_ih_next   (in place, own slice)
// Ring h traffic is L2-only (.cg stores/loads); publish is BAR2 + tid0
// st.release.gpu on the flag (no __threadfence / CCTL.IVALL on the step path).
// Gate topology is the R14-proven one: warp-0 lanes 0..7 poll with nanosleep.
// ==============================================================================
__global__ __launch_bounds__(256, 1) void rec_kernel(
    const float* __restrict__ Whh,        // [512][512] this layer
    const float* __restrict__ h0l,        // [32][512]  this layer
    const float* __restrict__ bhh,        // [512]      this layer
    const float* __restrict__ Wih_next,   // [512][512] next layer, or nullptr
    const float* __restrict__ bih_next,   // [512]      next layer, or nullptr
    float* __restrict__ outseq,           // [32][1024][512] or nullptr
    float* __restrict__ hidden_out,       // [32][512]  this layer
    int layer)
{
    const bool fuse = (Wih_next != nullptr);

    const int bg = blockIdx.x & (GB - 1);   // 0..15
    const int jg = blockIdx.x >> 4;         // 0..7
    const int b0 = bg * 2;
    const int jbase = jg * 64;

    const int tid  = threadIdx.x;
    const int w    = tid >> 5;              // warp -> 64-wide k chunk
    const int lane = tid & 31;

    __shared__ __align__(16) float h_sh[2][HID];   // [batch][k]
    __shared__ float red[8][2][64];                // [k-chunk][batch][jlocal]
    extern __shared__ float Wi_sh[];               // [64][WI_PAD] fused W_ih slice

    // ---- W_hh slice in registers, f32x2-packed along k ----
    unsigned long long Wr0[32], Wr1[32];
    {
        const float4* r0 = (const float4*)(Whh + (size_t)(jbase + lane) * HID + w * 64);
        const float4* r1 = (const float4*)(Whh + (size_t)(jbase + lane + 32) * HID + w * 64);
        #pragma unroll
        for (int i = 0; i < 16; i++) {
            float4 v0 = r0[i];
            Wr0[2 * i]     = pack2(v0.x, v0.y);
            Wr0[2 * i + 1] = pack2(v0.z, v0.w);
            float4 v1 = r1[i];
            Wr1[2 * i]     = pack2(v1.x, v1.y);
            Wr1[2 * i + 1] = pack2(v1.z, v1.w);
        }
    }

    // ---- fused W_ih slice into SMEM (rows jbase..jbase+63, padded stride) ----
    if (fuse) {
        for (int idx = tid; idx < 64 * (HID / 4); idx += 256) {
            int row = idx >> 7;             // /128
            int q   = (idx & 127) * 4;
            float4 v = *(const float4*)(Wih_next + (size_t)(jbase + row) * HID + q);
            *(float4*)&Wi_sh[(size_t)row * WI_PAD + q] = v;
        }
    }

    int* my_flag = &g_flags[layer][bg * GJ + jg];
    const int* flags_l = &g_flags[layer][bg * GJ];

    // Reduce mapping: tid<128 -> output (batch ob, column jl)
    const int ob = tid >> 6;
    const int jl = tid & 63;
    const float bias_r  = (tid < 128) ? bhh[jbase + jl] : 0.f;
    const float bias_in = (fuse && tid < 128) ? bih_next[jbase + jl] : 0.f;
    float* prow = g_P + ((size_t)(b0 + ob) * SEQ) * HID + jbase + jl;

    // Cooperative h load mapping: thread -> (batch, float4 of k)
    const int cb = tid >> 7;                // 0/1
    const int ck = (tid & 127) * 4;

    const int TMAX = fuse ? SEQ + 1 : SEQ;

    for (int t = 0; t < TMAX; t++) {
        const bool rec_step = (t < SEQ);

        // Pre-activation prefetch (DRAM latency overlapped with gate + load)
        float pre_v = 0.f;
        if (rec_step && tid < 128) pre_v = ldg_nc_f32(prow + (size_t)t * HID);

        // ---- gate + cooperative load of full h_{t-1} ----
        if (t == 0) {
            float4 v = *(const float4*)(h0l + (size_t)(b0 + cb) * HID + ck);
            *(float4*)&h_sh[cb][ck] = v;
        } else {
            if (tid < GJ) {
                while (ld_acquire_gpu(&flags_l[tid]) < t) __nanosleep(32);
            }
            __syncthreads();
            const float* hb = g_hbuf[(t - 1) & 1];
            float4 v = ldg_cg_f32x4(hb + (size_t)(b0 + cb) * HID + ck);
            *(float4*)&h_sh[cb][ck] = v;
        }
        __syncthreads();

        float val = 0.f;
        if (rec_step) {
            // ---- recurrent dot over this warp's 64-wide k chunk ----
            const unsigned long long* hA = (const unsigned long long*)(&h_sh[0][w * 64]);
            const unsigned long long* hB = (const unsigned long long*)(&h_sh[1][w * 64]);
            unsigned long long a00 = 0ull, a01 = 0ull, a10 = 0ull, a11 = 0ull;
            #pragma unroll
            for (int kk = 0; kk < 32; kk++) {
                unsigned long long ha = hA[kk];
                unsigned long long hb = hB[kk];
                a00 = ffma2(Wr0[kk], ha, a00);
                a01 = ffma2(Wr0[kk], hb, a01);
                a10 = ffma2(Wr1[kk], ha, a10);
                a11 = ffma2(Wr1[kk], hb, a11);
            }
            red[w][0][lane]      = pairsum(a00);
            red[w][1][lane]      = pairsum(a01);
            red[w][0][lane + 32] = pairsum(a10);
            red[w][1][lane + 32] = pairsum(a11);
            __syncthreads();                   // BAR1

            // ---- reduce, tanh, ring store (.cg: L2-only) ----
            if (tid < 128) {
                float s = pre_v + bias_r;
                #pragma unroll
                for (int ww = 0; ww < 8; ww++) s += red[ww][ob][jl];
                val = tanhf(s);
                if (fuse ? true : (t < SEQ - 1))
                    stg_cg_f32(&g_hbuf[t & 1][(size_t)(b0 + ob) * HID + jbase + jl], val);
            }
            __syncthreads();                   // BAR2: ring stores before release

            // ---- fence-free release: bar edge + release store on flag ----
            if (tid == 0 && (fuse ? (t < SEQ) : (t < SEQ - 1))) {
                st_release_gpu(my_flag, t + 1);
            }

            // ---- off-critical-path DRAM stores ----
            if (tid < 128) {
                if (outseq)
                    outseq[((size_t)(b0 + ob) * SEQ + t) * HID + jbase + jl] = val;
                if (t == SEQ - 1)
                    hidden_out[(size_t)(b0 + ob) * HID + jbase + jl] = val;
            }
        }

        // ---- fused next-layer projection for row t-1 (post-release slack) ----
        if (fuse && t > 0) {
            const unsigned long long* hA = (const unsigned long long*)(&h_sh[0][w * 64]);
            const unsigned long long* hB = (const unsigned long long*)(&h_sh[1][w * 64]);
            const unsigned long long* w0 =
                (const unsigned long long*)(&Wi_sh[(size_t)lane * WI_PAD + w * 64]);
            const unsigned long long* w1 =
                (const unsigned long long*)(&Wi_sh[(size_t)(lane + 32) * WI_PAD + w * 64]);
            unsigned long long a00 = 0ull, a01 = 0ull, a10 = 0ull, a11 = 0ull;
            #pragma unroll
            for (int kk = 0; kk < 32; kk++) {
                unsigned long long ha = hA[kk];
                unsigned long long hb = hB[kk];
                a00 = ffma2(w0[kk], ha, a00);
                a01 = ffma2(w0[kk], hb, a01);
                a10 = ffma2(w1[kk], ha, a10);
                a11 = ffma2(w1[kk], hb, a11);
            }
            red[w][0][lane]      = pairsum(a00);
            red[w][1][lane]      = pairsum(a01);
            red[w][0][lane + 32] = pairsum(a10);
            red[w][1][lane + 32] = pairsum(a11);
            __syncthreads();                   // BAR3

            if (tid < 128) {
                float s = bias_in;
                #pragma unroll
                for (int ww = 0; ww < 8; ww++) s += red[ww][ob][jl];
                // in-place: this row+slice was consumed by THIS CTA at step t-1
                prow[(size_t)(t - 1) * HID] = s;
            }
            // h_sh/red reuse at t+1 is ordered by the gate barrier of t+1
        }
    }
}

// ==============================================================================
extern "C" void kernel_launch(void* const* d_in, const int* in_sizes, int n_in,
                              void* d_out, int out_size)
{
    const float* x     = (const float*)d_in[0];   // [32,1024,128]
    const float* h0    = (const float*)d_in[1];   // [3,32,512]
    const float* w_ih0 = (const float*)d_in[2];   // [512,128]
    const float* w_ihs = (const float*)d_in[3];   // [2,512,512]
    const float* w_hhs = (const float*)d_in[4];   // [3,512,512]
    const float* b_ihs = (const float*)d_in[5];   // [3,512]
    const float* b_hhs = (const float*)d_in[6];   // [3,512]

    float* out    = (float*)d_out;
    float* hidden = out;                                   // [3][32][512]
    float* outseq = out + (size_t)LAYERS * BATCH * HID;    // [32][1024][512]

    const int wi_smem = 64 * WI_PAD * 4;                   // 132 KB dynamic

    static int smem_set = 0;
    if (!smem_set) {
        cudaFuncSetAttribute(rec_kernel,
                             cudaFuncAttributeMaxDynamicSharedMemorySize, wi_smem);
        smem_set = 1;
    }

    // Layer-0 input projection (also resets all flags; stream-ordered)
    dim3 pg(HID / 128, (BATCH * SEQ) / 128);               // (4, 256)
    proj_kernel<<<pg, 256>>>(x, w_ih0, b_ihs, INDIM);

    // ---- layer 0: rec + fused proj for layer 1 ----
    rec_kernel<<<GB * GJ, 256, wi_smem>>>(
        w_hhs + (size_t)0 * HID * HID, h0 + (size_t)0 * BATCH * HID,
        b_hhs + 0 * HID,
        w_ihs + (size_t)0 * HID * HID, b_ihs + 1 * HID,
        nullptr, hidden + (size_t)0 * BATCH * HID, 0);

    // ---- layer 1: rec + fused proj for layer 2 ----
    rec_kernel<<<GB * GJ, 256, wi_smem>>>(
        w_hhs + (size_t)1 * HID * HID, h0 + (size_t)1 * BATCH * HID,
        b_hhs + 1 * HID,
        w_ihs + (size_t)1 * HID * HID, b_ihs + 2 * HID,
        nullptr, hidden + (size_t)1 * BATCH * HID, 1);

    // ---- layer 2: rec only, sequence straight into d_out ----
    rec_kernel<<<GB * GJ, 256, wi_smem>>>(
        w_hhs + (size_t)2 * HID * HID, h0 + (size_t)2 * BATCH * HID,
        b_hhs + 2 * HID,
        nullptr, nullptr,
        outseq, hidden + (size_t)2 * BATCH * HID, 2);
}